// round 15
// baseline (speedup 1.0000x reference)
#include <cuda_runtime.h>
#include <cuda_fp16.h>
#include <math_constants.h>
#include <cstdint>

// Problem constants
#define B_   16
#define T_   128
#define N_   50
#define D_   512
#define H_   8
#define DH   64
#define TOK  (B_ * T_ * N_)      // 102400 tokens
#define K3   (3 * D_)            // 1536

// ---------------------------------------------------------------------------
// Scratch (device globals: allocation-free per harness rules)
// ---------------------------------------------------------------------------
__device__ __half g_Act[(size_t)TOK * K3];   // H for QKV; later attn out / FFN mid
__device__ __half g_q[(size_t)TOK * D_];
__device__ __half g_k[(size_t)TOK * D_];
__device__ __half g_v[(size_t)TOK * D_];
// Transposed fp16 weights: [Wq;Wk;Wv] stacked (1536 rows x K=1536), then W1, W2.
#define WOFF1 2359296
#define WOFF2 2621440
__device__ __half g_Wh[2883584];

// ---------------------------------------------------------------------------
// helpers
// ---------------------------------------------------------------------------
__device__ __forceinline__ uint32_t smem_u32(const void* p) {
    uint32_t a;
    asm("{ .reg .u64 t; cvta.to.shared.u64 t, %1; cvt.u32.u64 %0, t; }"
        : "=r"(a) : "l"(p));
    return a;
}

#define LDSM_X4(r0, r1, r2, r3, addr)                                         \
    asm volatile("ldmatrix.sync.aligned.m8n8.x4.shared.b16 {%0,%1,%2,%3}, [%4];" \
                 : "=r"(r0), "=r"(r1), "=r"(r2), "=r"(r3) : "r"(addr))

#define LDSM_X4_T(r0, r1, r2, r3, addr)                                       \
    asm volatile("ldmatrix.sync.aligned.m8n8.x4.trans.shared.b16 {%0,%1,%2,%3}, [%4];" \
                 : "=r"(r0), "=r"(r1), "=r"(r2), "=r"(r3) : "r"(addr))

#define MMA16816(d, a, b)                                                     \
    asm volatile("mma.sync.aligned.m16n8k16.row.col.f32.f16.f16.f32 "         \
                 "{%0,%1,%2,%3}, {%4,%5,%6,%7}, {%8,%9}, {%0,%1,%2,%3};"      \
                 : "+f"((d)[0]), "+f"((d)[1]), "+f"((d)[2]), "+f"((d)[3])     \
                 : "r"((a)[0]), "r"((a)[1]), "r"((a)[2]), "r"((a)[3]),        \
                   "r"((b)[0]), "r"((b)[1]))

#define CP16(dst, src)                                                        \
    asm volatile("cp.async.cg.shared.global [%0], [%1], 16;"                  \
                 :: "r"(dst), "l"(src))

__device__ __forceinline__ uint32_t packh2(float x, float y) {
    __half2 h = __floats2half2_rn(x, y);
    return *(uint32_t*)&h;
}

// ---------------------------------------------------------------------------
// All weight transposes in one launch.
// ---------------------------------------------------------------------------
__global__ void wtrans_all_kernel(const float* __restrict__ Wq,
                                  const float* __restrict__ Wk,
                                  const float* __restrict__ Wv,
                                  const float* __restrict__ W1,
                                  const float* __restrict__ W2) {
    int idx = blockIdx.x * 256 + threadIdx.x;
    const float* src;
    float v;
    if (idx < WOFF1) {
        int sel = idx / 786432, i = idx - sel * 786432;
        int n = i / K3, k = i - n * K3;
        src = (sel == 0) ? Wq : (sel == 1) ? Wk : Wv;
        v = src[(size_t)k * 512 + n];
    } else {
        int j = idx - WOFF1;
        int sel = j >> 18, i = j & 262143;
        int n = i >> 9, k = i & 511;
        src = sel ? W2 : W1;
        v = src[(size_t)k * 512 + n];
    }
    g_Wh[idx] = __float2half_rn(v);
}

// ---------------------------------------------------------------------------
// H = concat(X, TLE) -> fp16, 8 elems/thread
// ---------------------------------------------------------------------------
__global__ void conv_H_kernel(const float* __restrict__ X,
                              const float* __restrict__ TLE) {
    size_t i = ((size_t)blockIdx.x * 256 + threadIdx.x) * 8;
    size_t tok = i / K3;
    int c = (int)(i % K3);
    const float* src = (c < D_) ? (X + tok * D_ + c)
                                : (TLE + tok * (size_t)(2 * D_) + (c - D_));
    float4 a = *(const float4*)src;
    float4 b = *(const float4*)(src + 4);
    float f[8] = {a.x, a.y, a.z, a.w, b.x, b.y, b.z, b.w};
    __half h[8];
#pragma unroll
    for (int j = 0; j < 8; j++) h[j] = __float2half_rn(f[j]);
    *(uint4*)(g_Act + i) = *(uint4*)h;
}

// ---------------------------------------------------------------------------
// Tensor-core GEMM: C[*,512] = act(A @ Wt^T + bias)
//   CTA 128x256, 8 warps (2x4), warp tile 64x64, BK=64.
//   NEW: 4-stage cp.async pipeline (3 groups in flight) to ride out
//   L2/DRAM latency spikes at chunk boundaries.
// ---------------------------------------------------------------------------
#define PSTR     72
#define ARR_A    (128 * PSTR * 2)
#define ARR_Bt   (256 * PSTR * 2)
#define STAGE_B  (ARR_A + ARR_Bt)
#define NSTAGE   4
#define SMEM_B   (NSTAGE * STAGE_B)        // 221184

template<int ACT, int HOUT, int KDIM>
__global__ void __launch_bounds__(256)
mma_gemm(const __half* __restrict__ A, const __half* __restrict__ Bh,
         const float* __restrict__ bias0, const float* __restrict__ bias1,
         const float* __restrict__ bias2,
         void* C0, void* C1, void* C2) {
    extern __shared__ char sm[];
    uint32_t sbase = smem_u32(sm);

    int tid = threadIdx.x, wid = tid >> 5, lane = tid & 31;
    int bx = blockIdx.x;
    int warpM = (wid >> 2) * 64;
    int warpN = (wid & 3) * 64;

    const __half* srcA = A  + (size_t)blockIdx.y * 128 * KDIM;
    const __half* srcB = Bh + (size_t)bx * 256 * KDIM;

    float acc[4][8][4];
#pragma unroll
    for (int i = 0; i < 4; i++)
#pragma unroll
        for (int j = 0; j < 8; j++)
#pragma unroll
            for (int e = 0; e < 4; e++) acc[i][j][e] = 0.f;

    auto issue = [&](int c) {
        uint32_t stb = sbase + (uint32_t)((c % NSTAGE) * STAGE_B);
        int k0 = c * 64;
#pragma unroll
        for (int j = 0; j < 12; j++) {
            int idx = tid + j * 256;
            const __half* g;
            uint32_t d;
            if (idx < 1024) {
                int r = idx >> 3, s = idx & 7;
                g = srcA + (size_t)r * KDIM + k0 + s * 8;
                d = stb + (uint32_t)(r * (PSTR * 2) + s * 16);
            } else {
                int r = (idx - 1024) >> 3, s = idx & 7;
                g = srcB + (size_t)r * KDIM + k0 + s * 8;
                d = stb + (uint32_t)(ARR_A + r * (PSTR * 2) + s * 16);
            }
            CP16(d, g);
        }
        asm volatile("cp.async.commit_group;");
    };

    uint32_t aoff = (uint32_t)((warpM + (lane & 15)) * (PSTR * 2) + (lane >> 4) * 16);
    uint32_t boff = (uint32_t)(ARR_A +
                    (warpN + ((lane >> 4) << 3) + (lane & 7)) * (PSTR * 2) +
                    ((lane >> 3) & 1) * 16);

    auto ldfrag = [&](uint32_t stage, int kk, uint32_t (*Af)[4], uint32_t (*Bf)[2]) {
#pragma unroll
        for (int mt = 0; mt < 4; mt++) {
            uint32_t ad = stage + aoff + mt * (16 * PSTR * 2) + kk * 32;
            LDSM_X4(Af[mt][0], Af[mt][1], Af[mt][2], Af[mt][3], ad);
        }
#pragma unroll
        for (int np = 0; np < 4; np++) {
            uint32_t bd = stage + boff + np * (16 * PSTR * 2) + kk * 32;
            LDSM_X4(Bf[2*np][0], Bf[2*np][1], Bf[2*np+1][0], Bf[2*np+1][1], bd);
        }
    };

    uint32_t ah[2][4][4], bh8[2][8][2];

    const int nch = KDIM / 64;
    issue(0);
    issue(1);
    issue(2);
    for (int c = 0; c < nch; c++) {
        // pending groups: {c .. min(nch, c+3)-1}; drain group c only.
        if (c + 3 < nch)      asm volatile("cp.async.wait_group 2;");
        else if (c + 2 < nch) asm volatile("cp.async.wait_group 2;");
        else if (c + 1 < nch) asm volatile("cp.async.wait_group 1;");
        else                  asm volatile("cp.async.wait_group 0;");
        __syncthreads();
        if (c + 3 < nch) issue(c + 3);

        uint32_t stage = sbase + (uint32_t)((c % NSTAGE) * STAGE_B);
        ldfrag(stage, 0, ah[0], bh8[0]);
#pragma unroll
        for (int kk = 0; kk < 4; kk++) {
            int cur = kk & 1;
            if (kk < 3) ldfrag(stage, kk + 1, ah[cur ^ 1], bh8[cur ^ 1]);
#pragma unroll
            for (int mt = 0; mt < 4; mt++)
#pragma unroll
                for (int nt = 0; nt < 8; nt++)
                    MMA16816(acc[mt][nt], ah[cur][mt], bh8[cur][nt]);
        }
    }

    int reg = bx >> 1;
    const float* bias = (reg == 0) ? bias0 : (reg == 1) ? bias1 : bias2;
    void* Cp          = (reg == 0) ? C0    : (reg == 1) ? C1    : C2;
    int row0 = blockIdx.y * 128 + warpM + (lane >> 2);
    int col0 = (bx & 1) * 256 + warpN + (lane & 3) * 2;
#pragma unroll
    for (int mt = 0; mt < 4; mt++) {
#pragma unroll
        for (int nt = 0; nt < 8; nt++) {
            int r = row0 + mt * 16;
            int cc = col0 + nt * 8;
            float b0 = bias[cc], b1 = bias[cc + 1];
            float2 d0, d1;
            d0.x = acc[mt][nt][0] + b0; d0.y = acc[mt][nt][1] + b1;
            d1.x = acc[mt][nt][2] + b0; d1.y = acc[mt][nt][3] + b1;
            if (ACT) {
                d0.x = fmaxf(d0.x, 0.f); d0.y = fmaxf(d0.y, 0.f);
                d1.x = fmaxf(d1.x, 0.f); d1.y = fmaxf(d1.y, 0.f);
            }
            if (HOUT) {
                __half* Ch = (__half*)Cp;
                *(__half2*)(Ch + (size_t)r * 512 + cc)       = __floats2half2_rn(d0.x, d0.y);
                *(__half2*)(Ch + (size_t)(r + 8) * 512 + cc) = __floats2half2_rn(d1.x, d1.y);
            } else {
                float* Cf = (float*)Cp;
                *(float2*)(Cf + (size_t)r * 512 + cc)       = d0;
                *(float2*)(Cf + (size_t)(r + 8) * 512 + cc) = d1;
            }
        }
    }
}

// ---------------------------------------------------------------------------
// Tensor-core causal attention, two-tile pipelined (R13-proven form).
// ---------------------------------------------------------------------------
#define ATT_ROWB 144
#define ATT_ARR  (128 * ATT_ROWB)      // 18432
#define ATT_BUF  (3 * ATT_ARR)         // 55296 per tile
#define ATT_SMEM (2 * ATT_BUF)         // 110592

__global__ void __launch_bounds__(256, 2)
attn_tc_kernel(const int* __restrict__ kpm,
               const __half* __restrict__ Q, const __half* __restrict__ Kp,
               const __half* __restrict__ V, __half* __restrict__ outp) {
    extern __shared__ char sm[];
    uint32_t sb = smem_u32(sm);

    int tid = threadIdx.x, wq = tid >> 5, lane = tid & 31;
    const size_t rstride = (size_t)N_ * D_;

    int    Ls[2];
    int    RNs[2];
    size_t bases[2];
#pragma unroll
    for (int t = 0; t < 2; t++) {
        int bid = blockIdx.x + t * 3200;
        int h = bid & 7;
        int n = (bid >> 3) % N_;
        int b = bid / (H_ * N_);
        Ls[t] = kpm[b];
        int RN = ((Ls[t] + 15) >> 4) << 4;
        RNs[t] = (RN > 128) ? 128 : RN;
        bases[t] = ((size_t)(b * T_) * N_ + n) * D_ + h * DH;
    }

#pragma unroll
    for (int t = 0; t < 2; t++) {
        uint32_t dstb = sb + t * ATT_BUF;
        size_t base = bases[t];
        int RN = RNs[t];
#pragma unroll
        for (int j = 0; j < 12; j++) {
            int idx = tid + j * 256;
            int arr = idx >> 10, rem = idx & 1023;
            int r = rem >> 3, s = rem & 7;
            if (arr == 0 || r < RN) {
                const __half* src = ((arr == 0) ? Q : (arr == 1) ? Kp : V)
                                    + base + (size_t)r * rstride + s * 8;
                CP16(dstb + (uint32_t)(arr * ATT_ARR + r * ATT_ROWB + s * 16), src);
            }
        }
        asm volatile("cp.async.commit_group;");
    }

#pragma unroll
    for (int t = 0; t < 2; t++) {
        if (t == 0) asm volatile("cp.async.wait_group 1;");
        else        asm volatile("cp.async.wait_group 0;");
        __syncthreads();

        uint32_t sbt = sb + t * ATT_BUF;
        int L = Ls[t];
        size_t base = bases[t];
        int kmax = min(wq, (L - 1) >> 4);

        uint32_t qa[4][4];
#pragma unroll
        for (int kt = 0; kt < 4; kt++) {
            uint32_t ad = sbt + (wq * 16 + (lane & 15)) * ATT_ROWB
                              + (kt * 16 + (lane >> 4) * 8) * 2;
            LDSM_X4(qa[kt][0], qa[kt][1], qa[kt][2], qa[kt][3], ad);
        }

        float sa[16][4];
#pragma unroll
        for (int nt2 = 0; nt2 < 8; nt2++) {
            if (nt2 > kmax) continue;
            sa[2*nt2][0] = sa[2*nt2][1] = sa[2*nt2][2] = sa[2*nt2][3] = 0.f;
            sa[2*nt2+1][0] = sa[2*nt2+1][1] = sa[2*nt2+1][2] = sa[2*nt2+1][3] = 0.f;
#pragma unroll
            for (int kt = 0; kt < 4; kt++) {
                uint32_t bk0[2], bk1[2];
                uint32_t bd = sbt + ATT_ARR
                            + (nt2 * 16 + ((lane >> 4) << 3) + (lane & 7)) * ATT_ROWB
                            + (kt * 16 + ((lane >> 3) & 1) * 8) * 2;
                LDSM_X4(bk0[0], bk0[1], bk1[0], bk1[1], bd);
                MMA16816(sa[2 * nt2],     qa[kt], bk0);
                MMA16816(sa[2 * nt2 + 1], qa[kt], bk1);
            }
        }

        const float NEGINF = -CUDART_INF_F;
        int r0 = wq * 16 + (lane >> 2);
        int r1 = r0 + 8;
        int c2 = (lane & 3) * 2;
        float m0 = NEGINF, m1 = NEGINF;
#pragma unroll
        for (int nt = 0; nt < 16; nt++) {
            if ((nt >> 1) > kmax) continue;
            int c0 = nt * 8 + c2;
#pragma unroll
            for (int e = 0; e < 4; e++) {
                int col = c0 + (e & 1);
                int row = (e < 2) ? r0 : r1;
                float s = sa[nt][e] * 0.125f;
                if (col > row || col >= L) s = NEGINF;
                sa[nt][e] = s;
                if (e < 2) m0 = fmaxf(m0, s); else m1 = fmaxf(m1, s);
            }
        }
        m0 = fmaxf(m0, __shfl_xor_sync(0xffffffffu, m0, 1));
        m0 = fmaxf(m0, __shfl_xor_sync(0xffffffffu, m0, 2));
        m1 = fmaxf(m1, __shfl_xor_sync(0xffffffffu, m1, 1));
        m1 = fmaxf(m1, __shfl_xor_sync(0xffffffffu, m1, 2));

        float l0 = 0.f, l1 = 0.f;
#pragma unroll
        for (int nt = 0; nt < 16; nt++) {
            if ((nt >> 1) > kmax) continue;
#pragma unroll
            for (int e = 0; e < 4; e++) {
                float p = __expf(sa[nt][e] - ((e < 2) ? m0 : m1));
                sa[nt][e] = p;
                if (e < 2) l0 += p; else l1 += p;
            }
        }
        l0 += __shfl_xor_sync(0xffffffffu, l0, 1);
        l0 += __shfl_xor_sync(0xffffffffu, l0, 2);
        l1 += __shfl_xor_sync(0xffffffffu, l1, 1);
        l1 += __shfl_xor_sync(0xffffffffu, l1, 2);

        float oa[8][4];
#pragma unroll
        for (int dt = 0; dt < 8; dt++)
#pragma unroll
            for (int e = 0; e < 4; e++) oa[dt][e] = 0.f;

#pragma unroll
        for (int kt = 0; kt < 8; kt++) {
            if (kt > kmax) continue;
            uint32_t pa[4];
            pa[0] = packh2(sa[2 * kt][0],     sa[2 * kt][1]);
            pa[1] = packh2(sa[2 * kt][2],     sa[2 * kt][3]);
            pa[2] = packh2(sa[2 * kt + 1][0], sa[2 * kt + 1][1]);
            pa[3] = packh2(sa[2 * kt + 1][2], sa[2 * kt + 1][3]);
#pragma unroll
            for (int dt2 = 0; dt2 < 4; dt2++) {
                uint32_t bv0[2], bv1[2];
                uint32_t bd = sbt + 2 * ATT_ARR
                            + (kt * 16 + ((lane >> 3) & 1) * 8 + (lane & 7)) * ATT_ROWB
                            + (dt2 * 16 + ((lane >> 4) << 3)) * 2;
                LDSM_X4_T(bv0[0], bv0[1], bv1[0], bv1[1], bd);
                MMA16816(oa[2 * dt2],     pa, bv0);
                MMA16816(oa[2 * dt2 + 1], pa, bv1);
            }
        }

        float inv0 = 1.f / l0, inv1 = 1.f / l1;
        __half* op0 = outp + base + (size_t)r0 * rstride;
        __half* op1 = outp + base + (size_t)r1 * rstride;
#pragma unroll
        for (int dt = 0; dt < 8; dt++) {
            int c = dt * 8 + c2;
            *(__half2*)(op0 + c) = __floats2half2_rn(oa[dt][0] * inv0, oa[dt][1] * inv0);
            *(__half2*)(op1 + c) = __floats2half2_rn(oa[dt][2] * inv1, oa[dt][3] * inv1);
        }
    }
}

// ---------------------------------------------------------------------------
extern "C" void kernel_launch(void* const* d_in, const int* in_sizes, int n_in,
                              void* d_out, int out_size) {
    const float* X   = (const float*)d_in[0];
    const float* TLE = (const float*)d_in[1];
    const int*   kpm = (const int*)  d_in[2];
    const float* Wq  = (const float*)d_in[3];
    const float* bq  = (const float*)d_in[4];
    const float* Wk  = (const float*)d_in[5];
    const float* bk  = (const float*)d_in[6];
    const float* Wv  = (const float*)d_in[7];
    const float* bv  = (const float*)d_in[8];
    const float* W1  = (const float*)d_in[9];
    const float* b1  = (const float*)d_in[10];
    const float* W2  = (const float*)d_in[11];
    const float* b2  = (const float*)d_in[12];
    float* out = (float*)d_out;

    __half *pAct, *pWh, *pq, *pk, *pv;
    cudaGetSymbolAddress((void**)&pAct, g_Act);
    cudaGetSymbolAddress((void**)&pWh, g_Wh);
    cudaGetSymbolAddress((void**)&pq, g_q);
    cudaGetSymbolAddress((void**)&pk, g_k);
    cudaGetSymbolAddress((void**)&pv, g_v);

    __half* actR0 = pAct;                       // attn out / W1 input
    __half* actR1 = pAct + (size_t)TOK * D_;    // FFN mid

    cudaFuncSetAttribute((const void*)mma_gemm<1,1,1536>,
                         cudaFuncAttributeMaxDynamicSharedMemorySize, SMEM_B);
    cudaFuncSetAttribute((const void*)mma_gemm<1,1,512>,
                         cudaFuncAttributeMaxDynamicSharedMemorySize, SMEM_B);
    cudaFuncSetAttribute((const void*)mma_gemm<0,0,512>,
                         cudaFuncAttributeMaxDynamicSharedMemorySize, SMEM_B);
    cudaFuncSetAttribute((const void*)attn_tc_kernel,
                         cudaFuncAttributeMaxDynamicSharedMemorySize, ATT_SMEM);

    // 1. transpose all weights -> fp16 (single launch)
    wtrans_all_kernel<<<2883584 / 256, 256>>>(Wq, Wk, Wv, W1, W2);

    // 2. H = [X, TLE] -> fp16
    conv_H_kernel<<<(size_t)TOK * K3 / 8 / 256, 256>>>(X, TLE);

    // 3. fused QKV projection (single launch, 6 x 256-wide column blocks)
    mma_gemm<1,1,1536><<<dim3(6, TOK / 128), 256, SMEM_B>>>(
        pAct, pWh, bq, bk, bv, pq, pk, pv);

    // 4. tensor-core causal attention, two tiles per CTA -> fp16 region0
    attn_tc_kernel<<<B_ * N_ * H_ / 2, 256, ATT_SMEM>>>(kpm, pq, pk, pv, actR0);

    // 5. FFN
    mma_gemm<1,1,512><<<dim3(2, TOK / 128), 256, SMEM_B>>>(
        actR0, pWh + WOFF1, b1, b1, b1, actR1, actR1, actR1);
    mma_gemm<0,0,512><<<dim3(2, TOK / 128), 256, SMEM_B>>>(
        actR1, pWh + WOFF2, b2, b2, b2, out, out, out);
}

// round 17
// speedup vs baseline: 1.0494x; 1.0494x over previous
#include <cuda_runtime.h>
#include <cuda_fp16.h>
#include <math_constants.h>
#include <cstdint>

// Problem constants
#define B_   16
#define T_   128
#define N_   50
#define D_   512
#define H_   8
#define DH   64
#define TOK  (B_ * T_ * N_)      // 102400 tokens
#define K3   (3 * D_)            // 1536

// ---------------------------------------------------------------------------
// Scratch (device globals: allocation-free per harness rules)
// ---------------------------------------------------------------------------
__device__ __half g_Act[(size_t)TOK * K3];   // H for QKV; later attn out / FFN mid
__device__ __half g_q[(size_t)TOK * D_];
__device__ __half g_k[(size_t)TOK * D_];
__device__ __half g_v[(size_t)TOK * D_];
// Transposed fp16 weights: [Wq;Wk;Wv] stacked (1536 rows x K=1536), then W1, W2.
#define WOFF1 2359296
#define WOFF2 2621440
__device__ __half g_Wh[2883584];

// ---------------------------------------------------------------------------
// helpers
// ---------------------------------------------------------------------------
__device__ __forceinline__ uint32_t smem_u32(const void* p) {
    uint32_t a;
    asm("{ .reg .u64 t; cvta.to.shared.u64 t, %1; cvt.u32.u64 %0, t; }"
        : "=r"(a) : "l"(p));
    return a;
}

#define LDSM_X4(r0, r1, r2, r3, addr)                                         \
    asm volatile("ldmatrix.sync.aligned.m8n8.x4.shared.b16 {%0,%1,%2,%3}, [%4];" \
                 : "=r"(r0), "=r"(r1), "=r"(r2), "=r"(r3) : "r"(addr))

#define LDSM_X4_T(r0, r1, r2, r3, addr)                                       \
    asm volatile("ldmatrix.sync.aligned.m8n8.x4.trans.shared.b16 {%0,%1,%2,%3}, [%4];" \
                 : "=r"(r0), "=r"(r1), "=r"(r2), "=r"(r3) : "r"(addr))

#define MMA16816(d, a, b)                                                     \
    asm volatile("mma.sync.aligned.m16n8k16.row.col.f32.f16.f16.f32 "         \
                 "{%0,%1,%2,%3}, {%4,%5,%6,%7}, {%8,%9}, {%0,%1,%2,%3};"      \
                 : "+f"((d)[0]), "+f"((d)[1]), "+f"((d)[2]), "+f"((d)[3])     \
                 : "r"((a)[0]), "r"((a)[1]), "r"((a)[2]), "r"((a)[3]),        \
                   "r"((b)[0]), "r"((b)[1]))

#define CP16(dst, src)                                                        \
    asm volatile("cp.async.cg.shared.global [%0], [%1], 16;"                  \
                 :: "r"(dst), "l"(src))

__device__ __forceinline__ uint32_t packh2(float x, float y) {
    __half2 h = __floats2half2_rn(x, y);
    return *(uint32_t*)&h;
}

// ---------------------------------------------------------------------------
// All weight transposes in one launch.
// ---------------------------------------------------------------------------
__global__ void wtrans_all_kernel(const float* __restrict__ Wq,
                                  const float* __restrict__ Wk,
                                  const float* __restrict__ Wv,
                                  const float* __restrict__ W1,
                                  const float* __restrict__ W2) {
    int idx = blockIdx.x * 256 + threadIdx.x;
    const float* src;
    float v;
    if (idx < WOFF1) {
        int sel = idx / 786432, i = idx - sel * 786432;
        int n = i / K3, k = i - n * K3;
        src = (sel == 0) ? Wq : (sel == 1) ? Wk : Wv;
        v = src[(size_t)k * 512 + n];
    } else {
        int j = idx - WOFF1;
        int sel = j >> 18, i = j & 262143;
        int n = i >> 9, k = i & 511;
        src = sel ? W2 : W1;
        v = src[(size_t)k * 512 + n];
    }
    g_Wh[idx] = __float2half_rn(v);
}

// ---------------------------------------------------------------------------
// H = concat(X, TLE) -> fp16, 8 elems/thread
// ---------------------------------------------------------------------------
__global__ void conv_H_kernel(const float* __restrict__ X,
                              const float* __restrict__ TLE) {
    size_t i = ((size_t)blockIdx.x * 256 + threadIdx.x) * 8;
    size_t tok = i / K3;
    int c = (int)(i % K3);
    const float* src = (c < D_) ? (X + tok * D_ + c)
                                : (TLE + tok * (size_t)(2 * D_) + (c - D_));
    float4 a = *(const float4*)src;
    float4 b = *(const float4*)(src + 4);
    float f[8] = {a.x, a.y, a.z, a.w, b.x, b.y, b.z, b.w};
    __half h[8];
#pragma unroll
    for (int j = 0; j < 8; j++) h[j] = __float2half_rn(f[j]);
    *(uint4*)(g_Act + i) = *(uint4*)h;
}

// ---------------------------------------------------------------------------
// Tensor-core GEMM: C[*,512] = act(A @ Wt^T + bias)
//   NEW: CTA tile 128x128 (warp tile 64x32), 3-stage cp.async, ~125 regs,
//   110 KB smem -> 2 CTAs/SM. Cross-CTA residency hides the per-chunk
//   barrier/fill/drain overheads that single-residency exposed.
//   mma.sync peak needs only 96 B/cyc smem at this tile -> not smem-bound.
//   Output block select: rsel = bx>>2 picks (bias,C); (bx&3) is col block.
// ---------------------------------------------------------------------------
#define PSTR     72
#define ARR_X    (128 * PSTR * 2)          // 18432
#define STAGE_B  (2 * ARR_X)               // 36864 (A + B)
#define NSTAGE   3
#define SMEM_B   (NSTAGE * STAGE_B)        // 110592

template<int ACT, int HOUT, int KDIM>
__global__ void __launch_bounds__(256, 2)
mma_gemm(const __half* __restrict__ A, const __half* __restrict__ Bh,
         const float* __restrict__ bias0, const float* __restrict__ bias1,
         const float* __restrict__ bias2,
         void* C0, void* C1, void* C2) {
    extern __shared__ char sm[];
    uint32_t sbase = smem_u32(sm);

    int tid = threadIdx.x, wid = tid >> 5, lane = tid & 31;
    int bx = blockIdx.x;
    int warpM = (wid >> 2) * 64;           // 0 or 64
    int warpN = (wid & 3) * 32;            // 0,32,64,96

    const __half* srcA = A  + (size_t)blockIdx.y * 128 * KDIM;
    const __half* srcB = Bh + (size_t)bx * 128 * KDIM;

    float acc[4][4][4];
#pragma unroll
    for (int i = 0; i < 4; i++)
#pragma unroll
        for (int j = 0; j < 4; j++)
#pragma unroll
            for (int e = 0; e < 4; e++) acc[i][j][e] = 0.f;

    // copy: 2 arrays x 128 rows x 8 x 16B segs = 2048; 8 per thread
    auto issue = [&](int c) {
        uint32_t stb = sbase + (uint32_t)((c % NSTAGE) * STAGE_B);
        int k0 = c * 64;
#pragma unroll
        for (int j = 0; j < 8; j++) {
            int idx = tid + j * 256;
            int arr = idx >> 10, rem = idx & 1023;
            int r = rem >> 3, s = rem & 7;
            const __half* g = (arr ? srcB : srcA) + (size_t)r * KDIM + k0 + s * 8;
            CP16(stb + (uint32_t)(arr * ARR_X + r * (PSTR * 2) + s * 16), g);
        }
        asm volatile("cp.async.commit_group;");
    };

    uint32_t aoff = (uint32_t)((warpM + (lane & 15)) * (PSTR * 2) + (lane >> 4) * 16);
    uint32_t boff = (uint32_t)(ARR_X +
                    (warpN + ((lane >> 4) << 3) + (lane & 7)) * (PSTR * 2) +
                    ((lane >> 3) & 1) * 16);

    auto ldfrag = [&](uint32_t stage, int kk, uint32_t (*Af)[4], uint32_t (*Bf)[2]) {
#pragma unroll
        for (int mt = 0; mt < 4; mt++) {
            uint32_t ad = stage + aoff + mt * (16 * PSTR * 2) + kk * 32;
            LDSM_X4(Af[mt][0], Af[mt][1], Af[mt][2], Af[mt][3], ad);
        }
#pragma unroll
        for (int np = 0; np < 2; np++) {
            uint32_t bd = stage + boff + np * (16 * PSTR * 2) + kk * 32;
            LDSM_X4(Bf[2*np][0], Bf[2*np][1], Bf[2*np+1][0], Bf[2*np+1][1], bd);
        }
    };

    uint32_t ah[2][4][4], bh4[2][4][2];

    const int nch = KDIM / 64;
    issue(0);
    issue(1);
    for (int c = 0; c < nch; c++) {
        if (c + 1 < nch) asm volatile("cp.async.wait_group 1;");
        else             asm volatile("cp.async.wait_group 0;");
        __syncthreads();
        if (c + 2 < nch) issue(c + 2);

        uint32_t stage = sbase + (uint32_t)((c % NSTAGE) * STAGE_B);
        ldfrag(stage, 0, ah[0], bh4[0]);
#pragma unroll
        for (int kk = 0; kk < 4; kk++) {
            int cur = kk & 1;
            if (kk < 3) ldfrag(stage, kk + 1, ah[cur ^ 1], bh4[cur ^ 1]);
#pragma unroll
            for (int mt = 0; mt < 4; mt++)
#pragma unroll
                for (int nt = 0; nt < 4; nt++)
                    MMA16816(acc[mt][nt], ah[cur][mt], bh4[cur][nt]);
        }
    }

    int rsel = bx >> 2;
    const float* bias = (rsel == 0) ? bias0 : (rsel == 1) ? bias1 : bias2;
    void* Cp          = (rsel == 0) ? C0    : (rsel == 1) ? C1    : C2;
    int row0 = blockIdx.y * 128 + warpM + (lane >> 2);
    int col0 = (bx & 3) * 128 + warpN + (lane & 3) * 2;
#pragma unroll
    for (int mt = 0; mt < 4; mt++) {
#pragma unroll
        for (int nt = 0; nt < 4; nt++) {
            int r = row0 + mt * 16;
            int cc = col0 + nt * 8;
            float b0 = bias[cc], b1 = bias[cc + 1];
            float2 d0, d1;
            d0.x = acc[mt][nt][0] + b0; d0.y = acc[mt][nt][1] + b1;
            d1.x = acc[mt][nt][2] + b0; d1.y = acc[mt][nt][3] + b1;
            if (ACT) {
                d0.x = fmaxf(d0.x, 0.f); d0.y = fmaxf(d0.y, 0.f);
                d1.x = fmaxf(d1.x, 0.f); d1.y = fmaxf(d1.y, 0.f);
            }
            if (HOUT) {
                __half* Ch = (__half*)Cp;
                *(__half2*)(Ch + (size_t)r * 512 + cc)       = __floats2half2_rn(d0.x, d0.y);
                *(__half2*)(Ch + (size_t)(r + 8) * 512 + cc) = __floats2half2_rn(d1.x, d1.y);
            } else {
                float* Cf = (float*)Cp;
                *(float2*)(Cf + (size_t)r * 512 + cc)       = d0;
                *(float2*)(Cf + (size_t)(r + 8) * 512 + cc) = d1;
            }
        }
    }
}

// ---------------------------------------------------------------------------
// Tensor-core causal attention, two-tile pipelined (R13-proven form).
// ---------------------------------------------------------------------------
#define ATT_ROWB 144
#define ATT_ARR  (128 * ATT_ROWB)      // 18432
#define ATT_BUF  (3 * ATT_ARR)         // 55296 per tile
#define ATT_SMEM (2 * ATT_BUF)         // 110592

__global__ void __launch_bounds__(256, 2)
attn_tc_kernel(const int* __restrict__ kpm,
               const __half* __restrict__ Q, const __half* __restrict__ Kp,
               const __half* __restrict__ V, __half* __restrict__ outp) {
    extern __shared__ char sm[];
    uint32_t sb = smem_u32(sm);

    int tid = threadIdx.x, wq = tid >> 5, lane = tid & 31;
    const size_t rstride = (size_t)N_ * D_;

    int    Ls[2];
    int    RNs[2];
    size_t bases[2];
#pragma unroll
    for (int t = 0; t < 2; t++) {
        int bid = blockIdx.x + t * 3200;
        int h = bid & 7;
        int n = (bid >> 3) % N_;
        int b = bid / (H_ * N_);
        Ls[t] = kpm[b];
        int RN = ((Ls[t] + 15) >> 4) << 4;
        RNs[t] = (RN > 128) ? 128 : RN;
        bases[t] = ((size_t)(b * T_) * N_ + n) * D_ + h * DH;
    }

#pragma unroll
    for (int t = 0; t < 2; t++) {
        uint32_t dstb = sb + t * ATT_BUF;
        size_t base = bases[t];
        int RN = RNs[t];
#pragma unroll
        for (int j = 0; j < 12; j++) {
            int idx = tid + j * 256;
            int arr = idx >> 10, rem = idx & 1023;
            int r = rem >> 3, s = rem & 7;
            if (arr == 0 || r < RN) {
                const __half* src = ((arr == 0) ? Q : (arr == 1) ? Kp : V)
                                    + base + (size_t)r * rstride + s * 8;
                CP16(dstb + (uint32_t)(arr * ATT_ARR + r * ATT_ROWB + s * 16), src);
            }
        }
        asm volatile("cp.async.commit_group;");
    }

#pragma unroll
    for (int t = 0; t < 2; t++) {
        if (t == 0) asm volatile("cp.async.wait_group 1;");
        else        asm volatile("cp.async.wait_group 0;");
        __syncthreads();

        uint32_t sbt = sb + t * ATT_BUF;
        int L = Ls[t];
        size_t base = bases[t];
        int kmax = min(wq, (L - 1) >> 4);

        uint32_t qa[4][4];
#pragma unroll
        for (int kt = 0; kt < 4; kt++) {
            uint32_t ad = sbt + (wq * 16 + (lane & 15)) * ATT_ROWB
                              + (kt * 16 + (lane >> 4) * 8) * 2;
            LDSM_X4(qa[kt][0], qa[kt][1], qa[kt][2], qa[kt][3], ad);
        }

        float sa[16][4];
#pragma unroll
        for (int nt2 = 0; nt2 < 8; nt2++) {
            if (nt2 > kmax) continue;
            sa[2*nt2][0] = sa[2*nt2][1] = sa[2*nt2][2] = sa[2*nt2][3] = 0.f;
            sa[2*nt2+1][0] = sa[2*nt2+1][1] = sa[2*nt2+1][2] = sa[2*nt2+1][3] = 0.f;
#pragma unroll
            for (int kt = 0; kt < 4; kt++) {
                uint32_t bk0[2], bk1[2];
                uint32_t bd = sbt + ATT_ARR
                            + (nt2 * 16 + ((lane >> 4) << 3) + (lane & 7)) * ATT_ROWB
                            + (kt * 16 + ((lane >> 3) & 1) * 8) * 2;
                LDSM_X4(bk0[0], bk0[1], bk1[0], bk1[1], bd);
                MMA16816(sa[2 * nt2],     qa[kt], bk0);
                MMA16816(sa[2 * nt2 + 1], qa[kt], bk1);
            }
        }

        const float NEGINF = -CUDART_INF_F;
        int r0 = wq * 16 + (lane >> 2);
        int r1 = r0 + 8;
        int c2 = (lane & 3) * 2;
        float m0 = NEGINF, m1 = NEGINF;
#pragma unroll
        for (int nt = 0; nt < 16; nt++) {
            if ((nt >> 1) > kmax) continue;
            int c0 = nt * 8 + c2;
#pragma unroll
            for (int e = 0; e < 4; e++) {
                int col = c0 + (e & 1);
                int row = (e < 2) ? r0 : r1;
                float s = sa[nt][e] * 0.125f;
                if (col > row || col >= L) s = NEGINF;
                sa[nt][e] = s;
                if (e < 2) m0 = fmaxf(m0, s); else m1 = fmaxf(m1, s);
            }
        }
        m0 = fmaxf(m0, __shfl_xor_sync(0xffffffffu, m0, 1));
        m0 = fmaxf(m0, __shfl_xor_sync(0xffffffffu, m0, 2));
        m1 = fmaxf(m1, __shfl_xor_sync(0xffffffffu, m1, 1));
        m1 = fmaxf(m1, __shfl_xor_sync(0xffffffffu, m1, 2));

        float l0 = 0.f, l1 = 0.f;
#pragma unroll
        for (int nt = 0; nt < 16; nt++) {
            if ((nt >> 1) > kmax) continue;
#pragma unroll
            for (int e = 0; e < 4; e++) {
                float p = __expf(sa[nt][e] - ((e < 2) ? m0 : m1));
                sa[nt][e] = p;
                if (e < 2) l0 += p; else l1 += p;
            }
        }
        l0 += __shfl_xor_sync(0xffffffffu, l0, 1);
        l0 += __shfl_xor_sync(0xffffffffu, l0, 2);
        l1 += __shfl_xor_sync(0xffffffffu, l1, 1);
        l1 += __shfl_xor_sync(0xffffffffu, l1, 2);

        float oa[8][4];
#pragma unroll
        for (int dt = 0; dt < 8; dt++)
#pragma unroll
            for (int e = 0; e < 4; e++) oa[dt][e] = 0.f;

#pragma unroll
        for (int kt = 0; kt < 8; kt++) {
            if (kt > kmax) continue;
            uint32_t pa[4];
            pa[0] = packh2(sa[2 * kt][0],     sa[2 * kt][1]);
            pa[1] = packh2(sa[2 * kt][2],     sa[2 * kt][3]);
            pa[2] = packh2(sa[2 * kt + 1][0], sa[2 * kt + 1][1]);
            pa[3] = packh2(sa[2 * kt + 1][2], sa[2 * kt + 1][3]);
#pragma unroll
            for (int dt2 = 0; dt2 < 4; dt2++) {
                uint32_t bv0[2], bv1[2];
                uint32_t bd = sbt + 2 * ATT_ARR
                            + (kt * 16 + ((lane >> 3) & 1) * 8 + (lane & 7)) * ATT_ROWB
                            + (dt2 * 16 + ((lane >> 4) << 3)) * 2;
                LDSM_X4_T(bv0[0], bv0[1], bv1[0], bv1[1], bd);
                MMA16816(oa[2 * dt2],     pa, bv0);
                MMA16816(oa[2 * dt2 + 1], pa, bv1);
            }
        }

        float inv0 = 1.f / l0, inv1 = 1.f / l1;
        __half* op0 = outp + base + (size_t)r0 * rstride;
        __half* op1 = outp + base + (size_t)r1 * rstride;
#pragma unroll
        for (int dt = 0; dt < 8; dt++) {
            int c = dt * 8 + c2;
            *(__half2*)(op0 + c) = __floats2half2_rn(oa[dt][0] * inv0, oa[dt][1] * inv0);
            *(__half2*)(op1 + c) = __floats2half2_rn(oa[dt][2] * inv1, oa[dt][3] * inv1);
        }
    }
}

// ---------------------------------------------------------------------------
extern "C" void kernel_launch(void* const* d_in, const int* in_sizes, int n_in,
                              void* d_out, int out_size) {
    const float* X   = (const float*)d_in[0];
    const float* TLE = (const float*)d_in[1];
    const int*   kpm = (const int*)  d_in[2];
    const float* Wq  = (const float*)d_in[3];
    const float* bq  = (const float*)d_in[4];
    const float* Wk  = (const float*)d_in[5];
    const float* bk  = (const float*)d_in[6];
    const float* Wv  = (const float*)d_in[7];
    const float* bv  = (const float*)d_in[8];
    const float* W1  = (const float*)d_in[9];
    const float* b1  = (const float*)d_in[10];
    const float* W2  = (const float*)d_in[11];
    const float* b2  = (const float*)d_in[12];
    float* out = (float*)d_out;

    __half *pAct, *pWh, *pq, *pk, *pv;
    cudaGetSymbolAddress((void**)&pAct, g_Act);
    cudaGetSymbolAddress((void**)&pWh, g_Wh);
    cudaGetSymbolAddress((void**)&pq, g_q);
    cudaGetSymbolAddress((void**)&pk, g_k);
    cudaGetSymbolAddress((void**)&pv, g_v);

    __half* actR0 = pAct;                       // attn out / W1 input
    __half* actR1 = pAct + (size_t)TOK * D_;    // FFN mid

    cudaFuncSetAttribute((const void*)mma_gemm<1,1,1536>,
                         cudaFuncAttributeMaxDynamicSharedMemorySize, SMEM_B);
    cudaFuncSetAttribute((const void*)mma_gemm<1,1,512>,
                         cudaFuncAttributeMaxDynamicSharedMemorySize, SMEM_B);
    cudaFuncSetAttribute((const void*)mma_gemm<0,0,512>,
                         cudaFuncAttributeMaxDynamicSharedMemorySize, SMEM_B);
    cudaFuncSetAttribute((const void*)attn_tc_kernel,
                         cudaFuncAttributeMaxDynamicSharedMemorySize, ATT_SMEM);

    // 1. transpose all weights -> fp16 (single launch)
    wtrans_all_kernel<<<2883584 / 256, 256>>>(Wq, Wk, Wv, W1, W2);

    // 2. H = [X, TLE] -> fp16
    conv_H_kernel<<<(size_t)TOK * K3 / 8 / 256, 256>>>(X, TLE);

    // 3. fused QKV projection (12 x 128-wide column blocks; bx>>2 -> q/k/v)
    mma_gemm<1,1,1536><<<dim3(12, TOK / 128), 256, SMEM_B>>>(
        pAct, pWh, bq, bk, bv, pq, pk, pv);

    // 4. tensor-core causal attention, two tiles per CTA -> fp16 region0
    attn_tc_kernel<<<B_ * N_ * H_ / 2, 256, ATT_SMEM>>>(kpm, pq, pk, pv, actR0);

    // 5. FFN (4 x 128-wide column blocks each)
    mma_gemm<1,1,512><<<dim3(4, TOK / 128), 256, SMEM_B>>>(
        actR0, pWh + WOFF1, b1, b1, b1, actR1, actR1, actR1);
    mma_gemm<0,0,512><<<dim3(4, TOK / 128), 256, SMEM_B>>>(
        actR1, pWh + WOFF2, b2, b2, b2, out, out, out);
}